// round 9
// baseline (speedup 1.0000x reference)
#include <cuda_runtime.h>
#include <cuda_bf16.h>
#include <cstdint>

// ---------------------------------------------------------------------------
// Problem constants
// ---------------------------------------------------------------------------
#define D          128
#define N0_NODES   1081344
#define N1_NODES   67584
#define N2_NODES   6144
#define N3_NODES   1024
#define F0         15
#define F1         10
#define F2         5

// Scratch (no cudaMalloc allowed)
__device__ float g_agg[N1_NODES * D];
__device__ float g_P  [N1_NODES * D];
__device__ float g_h1 [N1_NODES * D];
__device__ float g_h2 [N2_NODES * D];
// 6 tf32 weight images (Wl0,Wr0,Wl1,Wr1,Wl2,Wr2), each [128 n][132 words]
#define IMG_WORDS (128 * 132)
__device__ float g_Bimg[6 * IMG_WORDS];

// ---------------------------------------------------------------------------
// Aggregation: warp per target, mean of F gathered 512B rows. (control)
// ---------------------------------------------------------------------------
template <int F>
__global__ void __launch_bounds__(256) agg_kernel(
    const float* __restrict__ x, const int* __restrict__ src,
    float* __restrict__ agg, int nt)
{
    int warp = blockIdx.x * 8 + (threadIdx.x >> 5);
    int lane = threadIdx.x & 31;
    if (warp >= nt) return;

    const float4* xv = reinterpret_cast<const float4*>(x);
    const int* sp = src + warp * F;

    int rows[F];
#pragma unroll
    for (int j = 0; j < F; j++) rows[j] = __ldg(sp + j);

    float4 s = make_float4(0.f, 0.f, 0.f, 0.f);
#pragma unroll
    for (int j = 0; j < F; j++) {
        float4 v = __ldg(&xv[(long)rows[j] * 32 + lane]);
        s.x += v.x; s.y += v.y; s.z += v.z; s.w += v.w;
    }
    const float invf = 1.0f / (float)F;
    s.x *= invf; s.y *= invf; s.z *= invf; s.w *= invf;
    reinterpret_cast<float4*>(agg)[(long)warp * 32 + lane] = s;
}

// ---------------------------------------------------------------------------
// helpers
// ---------------------------------------------------------------------------
__device__ __forceinline__ uint32_t f2tf32(float f) {
    uint32_t r;
    asm volatile("cvt.rna.tf32.f32 %0, %1;" : "=r"(r) : "f"(f));
    return r;
}
__device__ __forceinline__ void mma_tf32(float c[4], const uint32_t a[4],
                                         const uint32_t b[2]) {
    asm volatile(
        "mma.sync.aligned.m16n8k8.row.col.f32.tf32.tf32.f32 "
        "{%0,%1,%2,%3}, {%4,%5,%6,%7}, {%8,%9}, {%0,%1,%2,%3};"
        : "+f"(c[0]), "+f"(c[1]), "+f"(c[2]), "+f"(c[3])
        : "r"(a[0]), "r"(a[1]), "r"(a[2]), "r"(a[3]), "r"(b[0]), "r"(b[1]));
}
__device__ __forceinline__ void ldsm_x4(uint32_t a[4], uint32_t addr) {
    asm volatile("ldmatrix.sync.aligned.m8n8.x4.shared.b16 {%0,%1,%2,%3}, [%4];"
        : "=r"(a[0]), "=r"(a[1]), "=r"(a[2]), "=r"(a[3]) : "r"(addr));
}
__device__ __forceinline__ void ldsm_x2(uint32_t b[2], uint32_t addr) {
    asm volatile("ldmatrix.sync.aligned.m8n8.x2.shared.b16 {%0,%1}, [%2];"
        : "=r"(b[0]), "=r"(b[1]) : "r"(addr));
}
__device__ __forceinline__ void cp_async16(uint32_t saddr, const void* gptr) {
    asm volatile("cp.async.cg.shared.global [%0], [%1], 16;" ::
                 "r"(saddr), "l"(gptr));
}

// ---------------------------------------------------------------------------
// Weight pre-convert: 6 images of [128 n][128 k] -> tf32, stride 132 words
// ---------------------------------------------------------------------------
__global__ void __launch_bounds__(256) convert_B_all(
    const float* __restrict__ Wl0, const float* __restrict__ Wr0,
    const float* __restrict__ Wl1, const float* __restrict__ Wr1,
    const float* __restrict__ Wl2, const float* __restrict__ Wr2,
    float* __restrict__ img)
{
    int im  = blockIdx.x >> 6;               // 64 blocks per image
    int idx = (blockIdx.x & 63) * 256 + threadIdx.x;
    int n = idx >> 7;
    int k = idx & 127;
    const float* W =
        (im == 0) ? Wl0 : (im == 1) ? Wr0 :
        (im == 2) ? Wl1 : (im == 3) ? Wr1 :
        (im == 4) ? Wl2 : Wr2;
    *(uint32_t*)&img[(size_t)im * IMG_WORDS + n * 132 + k] =
        f2tf32(W[n * 128 + k]);
}

// ---------------------------------------------------------------------------
// Persistent K=128 GEMM: out[M,128] = A[M,128] @ Bimg^T (+P) (+act)
// 512 threads, 16 warps (4m x 4n), tile 128x128. B staged once per block;
// A pipelined as 4 chunks/tile of 32 k through a 4-buffer cp.async ring.
// ADD_P: epilogue adds P tile. MODE 0: raw store, 1: ReLU, 2: log_softmax
// (MODE 2 requires grid == numTiles).
// ---------------------------------------------------------------------------
#define AS_STRIDE 36
#define BS_STRIDE 132
#define AS_WORDS  (128 * AS_STRIDE)
#define BS_WORDS  (128 * BS_STRIDE)
#define SMEM_BYTES ((BS_WORDS + 4 * AS_WORDS) * 4)   // 141312

template <bool ADD_P, int MODE>
__global__ void __launch_bounds__(512, 1) gemm128(
    const float* __restrict__ A, const float* __restrict__ Bimg,
    const float* __restrict__ P, float* __restrict__ out, int numTiles)
{
    extern __shared__ uint32_t smem[];
    uint32_t* Bs = smem;                // [128 n][132] tf32
    uint32_t* As = smem + BS_WORDS;     // [4][128 m][36] raw fp32

    const int tid  = threadIdx.x;
    const int lane = tid & 31;
    const int wid  = tid >> 5;
    const int wm   = wid & 3;           // 4 warp rows x 32 m
    const int wn   = wid >> 2;          // 4 warp cols x 32 n

    const uint32_t as_base = (uint32_t)__cvta_generic_to_shared(As);
    const uint32_t bs_base = (uint32_t)__cvta_generic_to_shared(Bs);

    // ---- stage B image once ----
#pragma unroll
    for (int i = 0; i < 9; i++) {
        int e = i * 512 + tid;
        if (e < 128 * 33)
            cp_async16(bs_base + (uint32_t)e * 16,
                       (const uint8_t*)Bimg + (size_t)e * 16);
    }
    asm volatile("cp.async.commit_group;" ::);

    const int myTiles = (numTiles - blockIdx.x + gridDim.x - 1) / gridDim.x;
    const int totalQ  = myTiles * 4;         // 4 chunks of 32 k per tile

    auto issue = [&](int q) {
        const long blockM = (long)(blockIdx.x + (q >> 2) * gridDim.x) * 128;
        const int koff = (q & 3) * 32;
        const uint32_t sbase = as_base + (uint32_t)(q & 3) * (AS_WORDS * 4);
#pragma unroll
        for (int i = 0; i < 2; i++) {
            int idx = i * 512 + tid;       // 1024 segs: 128 rows x 8 segs
            int seg = idx & 7;
            int row = idx >> 3;
            cp_async16(sbase + (uint32_t)(row * (AS_STRIDE * 4) + seg * 16),
                       A + (blockM + row) * 128 + koff + seg * 4);
        }
        asm volatile("cp.async.commit_group;" ::);
    };

    issue(0);
    if (totalQ > 1) issue(1);
    if (totalQ > 2) issue(2);
    if (totalQ > 3) issue(3);

    float acc[2][4][4];
#pragma unroll
    for (int mi = 0; mi < 2; mi++)
#pragma unroll
        for (int ni = 0; ni < 4; ni++)
#pragma unroll
            for (int z = 0; z < 4; z++) acc[mi][ni][z] = 0.f;

    const uint32_t a_lane = (uint32_t)((wm * 32 + (lane & 15)) * (AS_STRIDE * 4)
                                       + (lane >> 4) * 16);
    const uint32_t b_lane = (uint32_t)((wn * 32 + (lane & 7)) * (BS_STRIDE * 4)
                                       + ((lane >> 3) & 1) * 16);

#pragma unroll 1
    for (int q = 0; q < totalQ; q++) {
        {
            int rem = totalQ - 1 - q;
            if (rem >= 3)      asm volatile("cp.async.wait_group 3;" ::);
            else if (rem == 2) asm volatile("cp.async.wait_group 2;" ::);
            else if (rem == 1) asm volatile("cp.async.wait_group 1;" ::);
            else               asm volatile("cp.async.wait_group 0;" ::);
        }
        __syncthreads();

        const uint32_t abuf = as_base + (uint32_t)(q & 3) * (AS_WORDS * 4);
        const int chunkK = (q & 3) * 32;
#pragma unroll
        for (int kb = 0; kb < 32; kb += 8) {
            const int gk = chunkK + kb;
            uint32_t bf[4][2];
#pragma unroll
            for (int ni = 0; ni < 4; ni++)
                ldsm_x2(bf[ni], bs_base + b_lane
                                + (uint32_t)(ni * 8 * BS_STRIDE * 4) + gk * 4);
            uint32_t af[2][4];
#pragma unroll
            for (int mi = 0; mi < 2; mi++) {
                ldsm_x4(af[mi], abuf + a_lane
                                + (uint32_t)(mi * 16 * AS_STRIDE * 4) + kb * 4);
#pragma unroll
                for (int z = 0; z < 4; z++)
                    asm volatile("cvt.rna.tf32.f32 %0, %0;" : "+r"(af[mi][z]));
            }
#pragma unroll
            for (int mi = 0; mi < 2; mi++)
#pragma unroll
                for (int ni = 0; ni < 4; ni++)
                    mma_tf32(acc[mi][ni], af[mi], bf[ni]);
        }
        __syncthreads();
        if (q + 4 < totalQ) issue(q + 4);

        if ((q & 3) == 3) {
            const long blockM = (long)(blockIdx.x + (q >> 2) * gridDim.x) * 128;

            if (ADD_P) {
#pragma unroll
                for (int mi = 0; mi < 2; mi++) {
#pragma unroll
                    for (int ni = 0; ni < 4; ni++) {
                        long row = blockM + wm * 32 + mi * 16 + (lane >> 2);
                        int  col = wn * 32 + ni * 8 + (lane & 3) * 2;
                        float2 p0 = *(const float2*)(P + row * 128 + col);
                        float2 p1 = *(const float2*)(P + (row + 8) * 128 + col);
                        acc[mi][ni][0] += p0.x; acc[mi][ni][1] += p0.y;
                        acc[mi][ni][2] += p1.x; acc[mi][ni][3] += p1.y;
                    }
                }
            }

            if (MODE <= 1) {
#pragma unroll
                for (int mi = 0; mi < 2; mi++) {
#pragma unroll
                    for (int ni = 0; ni < 4; ni++) {
                        long row = blockM + wm * 32 + mi * 16 + (lane >> 2);
                        int  col = wn * 32 + ni * 8 + (lane & 3) * 2;
                        float2 lo = make_float2(acc[mi][ni][0], acc[mi][ni][1]);
                        float2 hi = make_float2(acc[mi][ni][2], acc[mi][ni][3]);
                        if (MODE == 1) {
                            lo.x = fmaxf(lo.x, 0.f); lo.y = fmaxf(lo.y, 0.f);
                            hi.x = fmaxf(hi.x, 0.f); hi.y = fmaxf(hi.y, 0.f);
                        }
                        *(float2*)(out + row * 128 + col)       = lo;
                        *(float2*)(out + (row + 8) * 128 + col) = hi;
                    }
                }
            } else {
                // log_softmax epilogue (grid == numTiles)
                float* Ls = reinterpret_cast<float*>(As);   // [128][132]
#pragma unroll
                for (int mi = 0; mi < 2; mi++) {
#pragma unroll
                    for (int ni = 0; ni < 4; ni++) {
                        int row = wm * 32 + mi * 16 + (lane >> 2);
                        int col = wn * 32 + ni * 8 + (lane & 3) * 2;
                        *(float2*)(Ls + row * 132 + col) =
                            make_float2(acc[mi][ni][0], acc[mi][ni][1]);
                        *(float2*)(Ls + (row + 8) * 132 + col) =
                            make_float2(acc[mi][ni][2], acc[mi][ni][3]);
                    }
                }
                __syncthreads();
#pragma unroll 1
                for (int i = 0; i < 8; i++) {
                    int r = wid * 8 + i;
                    float4 v = *reinterpret_cast<float4*>(Ls + r * 132 + lane * 4);
                    float m = fmaxf(fmaxf(v.x, v.y), fmaxf(v.z, v.w));
#pragma unroll
                    for (int o = 16; o > 0; o >>= 1)
                        m = fmaxf(m, __shfl_xor_sync(0xFFFFFFFF, m, o));
                    float s = expf(v.x - m) + expf(v.y - m)
                            + expf(v.z - m) + expf(v.w - m);
#pragma unroll
                    for (int o = 16; o > 0; o >>= 1)
                        s += __shfl_xor_sync(0xFFFFFFFF, s, o);
                    float lse = m + logf(s);
                    float4 rr = make_float4(v.x - lse, v.y - lse,
                                            v.z - lse, v.w - lse);
                    *reinterpret_cast<float4*>(
                        out + (blockM + r) * 128 + lane * 4) = rr;
                }
            }
#pragma unroll
            for (int mi = 0; mi < 2; mi++)
#pragma unroll
                for (int ni = 0; ni < 4; ni++)
#pragma unroll
                    for (int z = 0; z < 4; z++) acc[mi][ni][z] = 0.f;
        }
    }
}

// ---------------------------------------------------------------------------
// Launch: fork P = X_self @ Wr^T onto a side stream, overlapping the gather.
// ---------------------------------------------------------------------------
extern "C" void kernel_launch(void* const* d_in, const int* in_sizes, int n_in,
                              void* d_out, int out_size)
{
    const long X_SZ = (long)N0_NODES * D;
    const int  W_SZ = D * D;

    const float* x = nullptr;
    const float* Wl[3] = {nullptr, nullptr, nullptr};
    const float* Wr[3] = {nullptr, nullptr, nullptr};
    const int*   src[3] = {nullptr, nullptr, nullptr};

    if ((long)in_sizes[0] == X_SZ && in_sizes[1] == W_SZ) {
        x = (const float*)d_in[0];
        for (int i = 0; i < 3; i++) {
            Wl[i]  = (const float*)d_in[1 + 2 * i];
            Wr[i]  = (const float*)d_in[2 + 2 * i];
            src[i] = (const int*)  d_in[7 + 2 * i];
        }
    } else if ((long)in_sizes[0] == X_SZ) {
        x = (const float*)d_in[0];
        for (int i = 0; i < 3; i++) {
            src[i] = (const int*)  d_in[1 + 4 * i];
            Wl[i]  = (const float*)d_in[3 + 4 * i];
            Wr[i]  = (const float*)d_in[4 + 4 * i];
        }
    } else {
        for (int i = 0; i < 3; i++) {
            Wl[i]  = (const float*)d_in[i];
            Wr[i]  = (const float*)d_in[3 + i];
            src[i] = (const int*)  d_in[9 + i];
        }
        x = (const float*)d_in[12];
    }

    float *agg, *P, *h1, *h2, *bimg;
    cudaGetSymbolAddress((void**)&agg,  g_agg);
    cudaGetSymbolAddress((void**)&P,    g_P);
    cudaGetSymbolAddress((void**)&h1,   g_h1);
    cudaGetSymbolAddress((void**)&h2,   g_h2);
    cudaGetSymbolAddress((void**)&bimg, g_Bimg);

    // One-time side stream + events (host resources; identical work per call)
    static cudaStream_t s2 = nullptr;
    static cudaEvent_t evF[3], evJ[3];
    if (!s2) {
        cudaStreamCreateWithFlags(&s2, cudaStreamNonBlocking);
        for (int i = 0; i < 3; i++) {
            cudaEventCreateWithFlags(&evF[i], cudaEventDisableTiming);
            cudaEventCreateWithFlags(&evJ[i], cudaEventDisableTiming);
        }
    }

    cudaFuncSetAttribute(gemm128<false, 0>,
        cudaFuncAttributeMaxDynamicSharedMemorySize, SMEM_BYTES);
    cudaFuncSetAttribute(gemm128<true, 1>,
        cudaFuncAttributeMaxDynamicSharedMemorySize, SMEM_BYTES);
    cudaFuncSetAttribute(gemm128<true, 2>,
        cudaFuncAttributeMaxDynamicSharedMemorySize, SMEM_BYTES);

    float* out = (float*)d_out;

    const int T0 = N1_NODES / 128;   // 528
    const int T1 = N2_NODES / 128;   // 48
    const int T2 = N3_NODES / 128;   // 8

    const float* WlI[3] = {bimg, bimg + 2 * IMG_WORDS, bimg + 4 * IMG_WORDS};
    const float* WrI[3] = {bimg + IMG_WORDS, bimg + 3 * IMG_WORDS,
                           bimg + 5 * IMG_WORDS};

    // Weight images (needed by both branches of layer 0)
    convert_B_all<<<384, 256>>>(Wl[0], Wr[0], Wl[1], Wr[1], Wl[2], Wr[2], bimg);

    // ---------------- Layer 0 ----------------
    cudaEventRecord(evF[0], 0);
    cudaStreamWaitEvent(s2, evF[0], 0);
    gemm128<false, 0><<<64, 512, SMEM_BYTES, s2>>>(x, WrI[0], nullptr, P, T0);
    agg_kernel<F0><<<N1_NODES / 8, 256>>>(x, src[0], agg, N1_NODES);
    cudaEventRecord(evJ[0], s2);
    cudaStreamWaitEvent(0, evJ[0], 0);
    gemm128<true, 1><<<132, 512, SMEM_BYTES>>>(agg, WlI[0], P, h1, T0);

    // ---------------- Layer 1 ----------------
    cudaEventRecord(evF[1], 0);
    cudaStreamWaitEvent(s2, evF[1], 0);
    gemm128<false, 0><<<24, 512, SMEM_BYTES, s2>>>(h1, WrI[1], nullptr, P, T1);
    agg_kernel<F1><<<N2_NODES / 8, 256>>>(h1, src[1], agg, N2_NODES);
    cudaEventRecord(evJ[1], s2);
    cudaStreamWaitEvent(0, evJ[1], 0);
    gemm128<true, 1><<<T1, 512, SMEM_BYTES>>>(agg, WlI[1], P, h2, T1);

    // ---------------- Layer 2 ----------------
    cudaEventRecord(evF[2], 0);
    cudaStreamWaitEvent(s2, evF[2], 0);
    gemm128<false, 0><<<T2, 512, SMEM_BYTES, s2>>>(h2, WrI[2], nullptr, P, T2);
    agg_kernel<F2><<<N3_NODES / 8, 256>>>(h2, src[2], agg, N3_NODES);
    cudaEventRecord(evJ[2], s2);
    cudaStreamWaitEvent(0, evJ[2], 0);
    gemm128<true, 2><<<T2, 512, SMEM_BYTES>>>(agg, WlI[2], P, out, T2);
}

// round 10
// speedup vs baseline: 1.0113x; 1.0113x over previous
#include <cuda_runtime.h>
#include <cuda_bf16.h>
#include <cstdint>

// ---------------------------------------------------------------------------
// Problem constants
// ---------------------------------------------------------------------------
#define D          128
#define N0_NODES   1081344
#define N1_NODES   67584
#define N2_NODES   6144
#define N3_NODES   1024
#define F0         15
#define F1         10
#define F2         5

// Scratch (no cudaMalloc allowed)
__device__ float g_agg[N1_NODES * D];
__device__ float g_h1 [N1_NODES * D];
__device__ float g_h2 [N2_NODES * D];
// Per-layer tf32 weight images [128 n][260 words] (k = 0..255 = [Wl;Wr])
#define IMG_WORDS (128 * 260)
__device__ float g_Bimg[3 * IMG_WORDS];

// ---------------------------------------------------------------------------
// Aggregation (layer 0 only): warp per target, mean of F rows. (control)
// ---------------------------------------------------------------------------
template <int F>
__global__ void __launch_bounds__(256) agg_kernel(
    const float* __restrict__ x, const int* __restrict__ src,
    float* __restrict__ agg, int nt)
{
    int warp = blockIdx.x * 8 + (threadIdx.x >> 5);
    int lane = threadIdx.x & 31;
    if (warp >= nt) return;

    const float4* xv = reinterpret_cast<const float4*>(x);
    const int* sp = src + warp * F;

    int rows[F];
#pragma unroll
    for (int j = 0; j < F; j++) rows[j] = __ldg(sp + j);

    float4 s = make_float4(0.f, 0.f, 0.f, 0.f);
#pragma unroll
    for (int j = 0; j < F; j++) {
        float4 v = __ldg(&xv[(long)rows[j] * 32 + lane]);
        s.x += v.x; s.y += v.y; s.z += v.z; s.w += v.w;
    }
    const float invf = 1.0f / (float)F;
    s.x *= invf; s.y *= invf; s.z *= invf; s.w *= invf;
    reinterpret_cast<float4*>(agg)[(long)warp * 32 + lane] = s;
}

// ---------------------------------------------------------------------------
// helpers
// ---------------------------------------------------------------------------
__device__ __forceinline__ uint32_t f2tf32(float f) {
    uint32_t r;
    asm volatile("cvt.rna.tf32.f32 %0, %1;" : "=r"(r) : "f"(f));
    return r;
}
__device__ __forceinline__ void mma_tf32(float c[4], const uint32_t a[4],
                                         const uint32_t b[2]) {
    asm volatile(
        "mma.sync.aligned.m16n8k8.row.col.f32.tf32.tf32.f32 "
        "{%0,%1,%2,%3}, {%4,%5,%6,%7}, {%8,%9}, {%0,%1,%2,%3};"
        : "+f"(c[0]), "+f"(c[1]), "+f"(c[2]), "+f"(c[3])
        : "r"(a[0]), "r"(a[1]), "r"(a[2]), "r"(a[3]), "r"(b[0]), "r"(b[1]));
}
__device__ __forceinline__ void ldsm_x4(uint32_t a[4], uint32_t addr) {
    asm volatile("ldmatrix.sync.aligned.m8n8.x4.shared.b16 {%0,%1,%2,%3}, [%4];"
        : "=r"(a[0]), "=r"(a[1]), "=r"(a[2]), "=r"(a[3]) : "r"(addr));
}
__device__ __forceinline__ void ldsm_x2(uint32_t b[2], uint32_t addr) {
    asm volatile("ldmatrix.sync.aligned.m8n8.x2.shared.b16 {%0,%1}, [%2];"
        : "=r"(b[0]), "=r"(b[1]) : "r"(addr));
}
__device__ __forceinline__ void cp_async16(uint32_t saddr, const void* gptr) {
    asm volatile("cp.async.cg.shared.global [%0], [%1], 16;" ::
                 "r"(saddr), "l"(gptr));
}

// ---------------------------------------------------------------------------
// Combined weight pre-convert: layer L image [n][260], k<256 = [Wl_L;Wr_L]
// ---------------------------------------------------------------------------
__global__ void __launch_bounds__(256) convert_B_all(
    const float* __restrict__ Wl0, const float* __restrict__ Wr0,
    const float* __restrict__ Wl1, const float* __restrict__ Wr1,
    const float* __restrict__ Wl2, const float* __restrict__ Wr2,
    float* __restrict__ img)
{
    int L = blockIdx.x >> 7;
    int idx = (blockIdx.x & 127) * 256 + threadIdx.x;
    int n = idx >> 8;
    int k = idx & 255;
    const float* Wl = (L == 0) ? Wl0 : (L == 1) ? Wl1 : Wl2;
    const float* Wr = (L == 0) ? Wr0 : (L == 1) ? Wr1 : Wr2;
    float w = (k < 128) ? Wl[n * 128 + k] : Wr[n * 128 + (k - 128)];
    *(uint32_t*)&img[(size_t)L * IMG_WORDS + n * 260 + k] = f2tf32(w);
}

// ---------------------------------------------------------------------------
// Layer-0 persistent dual GEMM (round-8 config, unchanged control):
// 512 threads, 16 warps (4m x 4n), tile 128x128, K=256, B image staged once,
// A = [Agg | X] pipelined as 8x32k chunks through a 4-buffer cp.async ring.
// ReLU epilogue.
// ---------------------------------------------------------------------------
#define AS_STRIDE 36
#define BS_STRIDE 260
#define AS_WORDS  (128 * AS_STRIDE)
#define BS_WORDS  (128 * BS_STRIDE)
#define SMEM_G0 ((BS_WORDS + 4 * AS_WORDS) * 4)      // 206848

__global__ void __launch_bounds__(512, 1) gemm_persist(
    const float* __restrict__ Aagg, const float* __restrict__ X,
    const float* __restrict__ Bimg, float* __restrict__ out, int numTiles)
{
    extern __shared__ uint32_t smem[];
    uint32_t* Bs = smem;
    uint32_t* As = smem + BS_WORDS;

    const int tid  = threadIdx.x;
    const int lane = tid & 31;
    const int wid  = tid >> 5;
    const int wm   = wid & 3;
    const int wn   = wid >> 2;

    const uint32_t as_base = (uint32_t)__cvta_generic_to_shared(As);
    const uint32_t bs_base = (uint32_t)__cvta_generic_to_shared(Bs);

#pragma unroll
    for (int i = 0; i < 17; i++) {
        int e = i * 512 + tid;
        if (e < 128 * 65)
            cp_async16(bs_base + (uint32_t)e * 16,
                       (const uint8_t*)Bimg + (size_t)e * 16);
    }
    asm volatile("cp.async.commit_group;" ::);

    const int myTiles = (numTiles - blockIdx.x + gridDim.x - 1) / gridDim.x;
    const int totalQ  = myTiles * 8;

    auto issue = [&](int q) {
        const int cc = q & 7;
        const long blockM = (long)(blockIdx.x + (q >> 3) * gridDim.x) * 128;
        const float* src = (cc < 4) ? Aagg : X;
        const int koff = (cc & 3) * 32;
        const uint32_t sbase = as_base + (uint32_t)(q & 3) * (AS_WORDS * 4);
#pragma unroll
        for (int i = 0; i < 2; i++) {
            int idx = i * 512 + tid;
            int seg = idx & 7;
            int row = idx >> 3;
            cp_async16(sbase + (uint32_t)(row * (AS_STRIDE * 4) + seg * 16),
                       src + (blockM + row) * 128 + koff + seg * 4);
        }
        asm volatile("cp.async.commit_group;" ::);
    };

    issue(0); issue(1); issue(2); issue(3);

    float acc[2][4][4];
#pragma unroll
    for (int mi = 0; mi < 2; mi++)
#pragma unroll
        for (int ni = 0; ni < 4; ni++)
#pragma unroll
            for (int z = 0; z < 4; z++) acc[mi][ni][z] = 0.f;

    const uint32_t a_lane = (uint32_t)((wm * 32 + (lane & 15)) * (AS_STRIDE * 4)
                                       + (lane >> 4) * 16);
    const uint32_t b_lane = (uint32_t)((wn * 32 + (lane & 7)) * (BS_STRIDE * 4)
                                       + ((lane >> 3) & 1) * 16);

#pragma unroll 1
    for (int q = 0; q < totalQ; q++) {
        {
            int rem = totalQ - 1 - q;
            if (rem >= 3)      asm volatile("cp.async.wait_group 3;" ::);
            else if (rem == 2) asm volatile("cp.async.wait_group 2;" ::);
            else if (rem == 1) asm volatile("cp.async.wait_group 1;" ::);
            else               asm volatile("cp.async.wait_group 0;" ::);
        }
        __syncthreads();

        const uint32_t abuf = as_base + (uint32_t)(q & 3) * (AS_WORDS * 4);
        const int chunkK = (q & 7) * 32;
#pragma unroll
        for (int kb = 0; kb < 32; kb += 8) {
            const int gk = chunkK + kb;
            uint32_t bf[4][2];
#pragma unroll
            for (int ni = 0; ni < 4; ni++)
                ldsm_x2(bf[ni], bs_base + b_lane
                                + (uint32_t)(ni * 8 * BS_STRIDE * 4) + gk * 4);
            uint32_t af[2][4];
#pragma unroll
            for (int mi = 0; mi < 2; mi++) {
                ldsm_x4(af[mi], abuf + a_lane
                                + (uint32_t)(mi * 16 * AS_STRIDE * 4) + kb * 4);
#pragma unroll
                for (int z = 0; z < 4; z++)
                    asm volatile("cvt.rna.tf32.f32 %0, %0;" : "+r"(af[mi][z]));
            }
#pragma unroll
            for (int mi = 0; mi < 2; mi++)
#pragma unroll
                for (int ni = 0; ni < 4; ni++)
                    mma_tf32(acc[mi][ni], af[mi], bf[ni]);
        }
        __syncthreads();
        if (q + 4 < totalQ) issue(q + 4);

        if ((q & 7) == 7) {
            const long blockM = (long)(blockIdx.x + (q >> 3) * gridDim.x) * 128;
#pragma unroll
            for (int mi = 0; mi < 2; mi++) {
#pragma unroll
                for (int ni = 0; ni < 4; ni++) {
                    long row = blockM + wm * 32 + mi * 16 + (lane >> 2);
                    int  col = wn * 32 + ni * 8 + (lane & 3) * 2;
                    float2 lo = make_float2(fmaxf(acc[mi][ni][0], 0.f),
                                            fmaxf(acc[mi][ni][1], 0.f));
                    float2 hi = make_float2(fmaxf(acc[mi][ni][2], 0.f),
                                            fmaxf(acc[mi][ni][3], 0.f));
                    *(float2*)(out + row * 128 + col)       = lo;
                    *(float2*)(out + (row + 8) * 128 + col) = hi;
                    acc[mi][ni][0] = acc[mi][ni][1] = 0.f;
                    acc[mi][ni][2] = acc[mi][ni][3] = 0.f;
                }
            }
        }
    }
}

// ---------------------------------------------------------------------------
// Fused layer kernel for small layers (verified round-3 structure, 16 warps):
// one block per 128 targets. Gather-mean -> tf32 A chunks 0/1; x-self chunks
// 2/3 via cp.async (cvt post-LDSM); B tf32 image (no cvt). K=256 MMA.
// MODE 0: ReLU -> out. MODE 1: log_softmax -> out.
// ---------------------------------------------------------------------------
#define FAS_STRIDE 68
#define FAS_WORDS  (128 * FAS_STRIDE)
#define SMEM_FUSED ((BS_WORDS + 2 * FAS_WORDS) * 4)   // 202752

template <int F, int MODE>
__global__ void __launch_bounds__(512, 1) fused_layer(
    const float* __restrict__ x, const int* __restrict__ src,
    const float* __restrict__ Bimg, float* __restrict__ out)
{
    extern __shared__ uint32_t smem[];
    uint32_t* Bs = smem;                 // [128 n][260] tf32
    uint32_t* As = smem + BS_WORDS;      // [2][128 m][68]

    const int tid  = threadIdx.x;
    const int lane = tid & 31;
    const int wid  = tid >> 5;
    const int wm   = wid & 3;
    const int wn   = wid >> 2;
    const long blockM = (long)blockIdx.x * 128;

    const uint32_t as_base = (uint32_t)__cvta_generic_to_shared(As);
    const uint32_t bs_base = (uint32_t)__cvta_generic_to_shared(Bs);

    // ---- B image (group 0), overlaps with gather ----
#pragma unroll
    for (int i = 0; i < 17; i++) {
        int e = i * 512 + tid;
        if (e < 128 * 65)
            cp_async16(bs_base + (uint32_t)e * 16,
                       (const uint8_t*)Bimg + (size_t)e * 16);
    }
    asm volatile("cp.async.commit_group;" ::);

    // ---- gather-mean: warp w -> targets w*8 .. w*8+7 ----
    {
        const float4* xv = reinterpret_cast<const float4*>(x);
        const float invf = 1.0f / (float)F;
#pragma unroll 1
        for (int i = 0; i < 8; i++) {
            int tr = wid * 8 + i;
            const int* sp = src + (blockM + tr) * F;
            int rows[F];
#pragma unroll
            for (int j = 0; j < F; j++) rows[j] = __ldg(sp + j);
            float4 s = make_float4(0.f, 0.f, 0.f, 0.f);
#pragma unroll
            for (int j = 0; j < F; j++) {
                float4 v = __ldg(&xv[(long)rows[j] * 32 + lane]);
                s.x += v.x; s.y += v.y; s.z += v.z; s.w += v.w;
            }
            uint4 t;
            t.x = f2tf32(s.x * invf); t.y = f2tf32(s.y * invf);
            t.z = f2tf32(s.z * invf); t.w = f2tf32(s.w * invf);
            int buf = lane >> 4;             // lanes 0-15: k<64, 16-31: k 64-127
            int kk  = (lane & 15) * 4;
            *reinterpret_cast<uint4*>(As + buf * FAS_WORDS
                                      + tr * FAS_STRIDE + kk) = t;
        }
    }

    float acc[2][4][4];
#pragma unroll
    for (int mi = 0; mi < 2; mi++)
#pragma unroll
        for (int ni = 0; ni < 4; ni++)
#pragma unroll
            for (int z = 0; z < 4; z++) acc[mi][ni][z] = 0.f;

    const uint32_t a_lane = (uint32_t)((wm * 32 + (lane & 15)) * (FAS_STRIDE * 4)
                                       + (lane >> 4) * 16);
    const uint32_t b_lane = (uint32_t)((wn * 32 + (lane & 7)) * (BS_STRIDE * 4)
                                       + ((lane >> 3) & 1) * 16);

    auto issue_x = [&](int c) {          // c = 2|3 -> buf c&1, koff (c&1)*64
        const int koff = (c & 1) * 64;
        const uint32_t sbase = as_base + (uint32_t)(c & 1) * (FAS_WORDS * 4);
#pragma unroll
        for (int i = 0; i < 4; i++) {
            int idx = i * 512 + tid;     // 2048 segs: 128 rows x 16 segs
            int seg = idx & 15;
            int row = idx >> 4;
            cp_async16(sbase + (uint32_t)(row * (FAS_STRIDE * 4) + seg * 16),
                       x + (blockM + row) * 128 + koff + seg * 4);
        }
        asm volatile("cp.async.commit_group;" ::);
    };

    auto mma_chunk = [&](int c, int buf, bool cvtA) {
        const uint32_t abuf = as_base + (uint32_t)buf * (FAS_WORDS * 4);
#pragma unroll
        for (int kb = 0; kb < 64; kb += 8) {
            const int gk = c * 64 + kb;
            uint32_t bf[4][2];
#pragma unroll
            for (int ni = 0; ni < 4; ni++)
                ldsm_x2(bf[ni], bs_base + b_lane
                                + (uint32_t)(ni * 8 * BS_STRIDE * 4) + gk * 4);
            uint32_t af[2][4];
#pragma unroll
            for (int mi = 0; mi < 2; mi++) {
                ldsm_x4(af[mi], abuf + a_lane
                                + (uint32_t)(mi * 16 * FAS_STRIDE * 4) + kb * 4);
                if (cvtA) {
#pragma unroll
                    for (int z = 0; z < 4; z++)
                        asm volatile("cvt.rna.tf32.f32 %0, %0;" : "+r"(af[mi][z]));
                }
            }
#pragma unroll
            for (int mi = 0; mi < 2; mi++)
#pragma unroll
                for (int ni = 0; ni < 4; ni++)
                    mma_tf32(acc[mi][ni], af[mi], bf[ni]);
        }
    };

    asm volatile("cp.async.wait_group 0;" ::);   // B resident
    __syncthreads();                             // gather STS visible

    mma_chunk(0, 0, false);
    __syncthreads();
    issue_x(2);
    mma_chunk(1, 1, false);
    __syncthreads();
    issue_x(3);
    asm volatile("cp.async.wait_group 1;" ::);
    __syncthreads();
    mma_chunk(2, 0, true);
    __syncthreads();
    asm volatile("cp.async.wait_group 0;" ::);
    __syncthreads();
    mma_chunk(3, 1, true);

    if (MODE == 0) {
#pragma unroll
        for (int mi = 0; mi < 2; mi++) {
#pragma unroll
            for (int ni = 0; ni < 4; ni++) {
                long row = blockM + wm * 32 + mi * 16 + (lane >> 2);
                int  col = wn * 32 + ni * 8 + (lane & 3) * 2;
                float2 lo = make_float2(fmaxf(acc[mi][ni][0], 0.f),
                                        fmaxf(acc[mi][ni][1], 0.f));
                float2 hi = make_float2(fmaxf(acc[mi][ni][2], 0.f),
                                        fmaxf(acc[mi][ni][3], 0.f));
                *(float2*)(out + row * 128 + col)       = lo;
                *(float2*)(out + (row + 8) * 128 + col) = hi;
            }
        }
    } else {
        float* Ls = reinterpret_cast<float*>(As);   // [128][132]
        __syncthreads();
#pragma unroll
        for (int mi = 0; mi < 2; mi++) {
#pragma unroll
            for (int ni = 0; ni < 4; ni++) {
                int row = wm * 32 + mi * 16 + (lane >> 2);
                int col = wn * 32 + ni * 8 + (lane & 3) * 2;
                *(float2*)(Ls + row * 132 + col) =
                    make_float2(acc[mi][ni][0], acc[mi][ni][1]);
                *(float2*)(Ls + (row + 8) * 132 + col) =
                    make_float2(acc[mi][ni][2], acc[mi][ni][3]);
            }
        }
        __syncthreads();
#pragma unroll 1
        for (int i = 0; i < 8; i++) {
            int r = wid * 8 + i;
            float4 v = *reinterpret_cast<float4*>(Ls + r * 132 + lane * 4);
            float m = fmaxf(fmaxf(v.x, v.y), fmaxf(v.z, v.w));
#pragma unroll
            for (int o = 16; o > 0; o >>= 1)
                m = fmaxf(m, __shfl_xor_sync(0xFFFFFFFF, m, o));
            float s = expf(v.x - m) + expf(v.y - m)
                    + expf(v.z - m) + expf(v.w - m);
#pragma unroll
            for (int o = 16; o > 0; o >>= 1)
                s += __shfl_xor_sync(0xFFFFFFFF, s, o);
            float lse = m + logf(s);
            float4 rr = make_float4(v.x - lse, v.y - lse, v.z - lse, v.w - lse);
            *reinterpret_cast<float4*>(out + (blockM + r) * 128 + lane * 4) = rr;
        }
    }
}

// ---------------------------------------------------------------------------
// Launch
// ---------------------------------------------------------------------------
extern "C" void kernel_launch(void* const* d_in, const int* in_sizes, int n_in,
                              void* d_out, int out_size)
{
    const long X_SZ = (long)N0_NODES * D;
    const int  W_SZ = D * D;

    const float* x = nullptr;
    const float* Wl[3] = {nullptr, nullptr, nullptr};
    const float* Wr[3] = {nullptr, nullptr, nullptr};
    const int*   src[3] = {nullptr, nullptr, nullptr};

    if ((long)in_sizes[0] == X_SZ && in_sizes[1] == W_SZ) {
        x = (const float*)d_in[0];
        for (int i = 0; i < 3; i++) {
            Wl[i]  = (const float*)d_in[1 + 2 * i];
            Wr[i]  = (const float*)d_in[2 + 2 * i];
            src[i] = (const int*)  d_in[7 + 2 * i];
        }
    } else if ((long)in_sizes[0] == X_SZ) {
        x = (const float*)d_in[0];
        for (int i = 0; i < 3; i++) {
            src[i] = (const int*)  d_in[1 + 4 * i];
            Wl[i]  = (const float*)d_in[3 + 4 * i];
            Wr[i]  = (const float*)d_in[4 + 4 * i];
        }
    } else {
        for (int i = 0; i < 3; i++) {
            Wl[i]  = (const float*)d_in[i];
            Wr[i]  = (const float*)d_in[3 + i];
            src[i] = (const int*)  d_in[9 + i];
        }
        x = (const float*)d_in[12];
    }

    float *agg, *h1, *h2, *bimg;
    cudaGetSymbolAddress((void**)&agg,  g_agg);
    cudaGetSymbolAddress((void**)&h1,   g_h1);
    cudaGetSymbolAddress((void**)&h2,   g_h2);
    cudaGetSymbolAddress((void**)&bimg, g_Bimg);

    cudaFuncSetAttribute(gemm_persist,
        cudaFuncAttributeMaxDynamicSharedMemorySize, SMEM_G0);
    cudaFuncSetAttribute(fused_layer<F1, 0>,
        cudaFuncAttributeMaxDynamicSharedMemorySize, SMEM_FUSED);
    cudaFuncSetAttribute(fused_layer<F2, 1>,
        cudaFuncAttributeMaxDynamicSharedMemorySize, SMEM_FUSED);

    float* out = (float*)d_out;

    const int T0 = N1_NODES / 128;   // 528 = 132 * 4

    // Weight images
    convert_B_all<<<384, 256>>>(Wl[0], Wr[0], Wl[1], Wr[1], Wl[2], Wr[2], bimg);

    // Layer 0: standalone roofline gather + persistent GEMM
    agg_kernel<F0><<<N1_NODES / 8, 256>>>(x, src[0], agg, N1_NODES);
    gemm_persist<<<132, 512, SMEM_G0>>>(agg, x, bimg, h1, T0);

    // Layer 1: fused gather + GEMM + ReLU
    fused_layer<F1, 0><<<N2_NODES / 128, 512, SMEM_FUSED>>>(
        h1, src[1], bimg + IMG_WORDS, h2);

    // Layer 2: fused gather + GEMM + log_softmax
    fused_layer<F2, 1><<<N3_NODES / 128, 512, SMEM_FUSED>>>(
        h2, src[2], bimg + 2 * IMG_WORDS, out);
}

// round 11
// speedup vs baseline: 1.0814x; 1.0693x over previous
#include <cuda_runtime.h>
#include <cuda_bf16.h>
#include <cstdint>

// ---------------------------------------------------------------------------
// Problem constants
// ---------------------------------------------------------------------------
#define D          128
#define N0_NODES   1081344
#define N1_NODES   67584
#define N2_NODES   6144
#define N3_NODES   1024
#define F0         15
#define F1         10
#define F2         5

// Scratch (no cudaMalloc allowed)
__device__ float g_agg[N1_NODES * D];
__device__ float g_h1 [N1_NODES * D];
__device__ float g_h2 [N2_NODES * D];
// Per-layer tf32 weight images [128 n][260 words] (k = 0..255 = [Wl;Wr])
#define IMG_WORDS (128 * 260)
__device__ float g_Bimg[3 * IMG_WORDS];

// ---------------------------------------------------------------------------
// Aggregation: warp per target, mean of F gathered 512B rows. (control)
// ---------------------------------------------------------------------------
template <int F>
__global__ void __launch_bounds__(256) agg_kernel(
    const float* __restrict__ x, const int* __restrict__ src,
    float* __restrict__ agg, int nt)
{
    int warp = blockIdx.x * 8 + (threadIdx.x >> 5);
    int lane = threadIdx.x & 31;
    if (warp >= nt) return;

    const float4* xv = reinterpret_cast<const float4*>(x);
    const int* sp = src + warp * F;

    int rows[F];
#pragma unroll
    for (int j = 0; j < F; j++) rows[j] = __ldg(sp + j);

    float4 s = make_float4(0.f, 0.f, 0.f, 0.f);
#pragma unroll
    for (int j = 0; j < F; j++) {
        float4 v = __ldg(&xv[(long)rows[j] * 32 + lane]);
        s.x += v.x; s.y += v.y; s.z += v.z; s.w += v.w;
    }
    const float invf = 1.0f / (float)F;
    s.x *= invf; s.y *= invf; s.z *= invf; s.w *= invf;
    reinterpret_cast<float4*>(agg)[(long)warp * 32 + lane] = s;
}

// ---------------------------------------------------------------------------
// helpers
// ---------------------------------------------------------------------------
__device__ __forceinline__ uint32_t f2tf32(float f) {
    uint32_t r;
    asm volatile("cvt.rna.tf32.f32 %0, %1;" : "=r"(r) : "f"(f));
    return r;
}
__device__ __forceinline__ void mma_tf32(float c[4], const uint32_t a[4],
                                         const uint32_t b[2]) {
    asm volatile(
        "mma.sync.aligned.m16n8k8.row.col.f32.tf32.tf32.f32 "
        "{%0,%1,%2,%3}, {%4,%5,%6,%7}, {%8,%9}, {%0,%1,%2,%3};"
        : "+f"(c[0]), "+f"(c[1]), "+f"(c[2]), "+f"(c[3])
        : "r"(a[0]), "r"(a[1]), "r"(a[2]), "r"(a[3]), "r"(b[0]), "r"(b[1]));
}
__device__ __forceinline__ void ldsm_x4(uint32_t a[4], uint32_t addr) {
    asm volatile("ldmatrix.sync.aligned.m8n8.x4.shared.b16 {%0,%1,%2,%3}, [%4];"
        : "=r"(a[0]), "=r"(a[1]), "=r"(a[2]), "=r"(a[3]) : "r"(addr));
}
__device__ __forceinline__ void ldsm_x2(uint32_t b[2], uint32_t addr) {
    asm volatile("ldmatrix.sync.aligned.m8n8.x2.shared.b16 {%0,%1}, [%2];"
        : "=r"(b[0]), "=r"(b[1]) : "r"(addr));
}
__device__ __forceinline__ void cp_async16(uint32_t saddr, const void* gptr) {
    asm volatile("cp.async.cg.shared.global [%0], [%1], 16;" ::
                 "r"(saddr), "l"(gptr));
}

// ---------------------------------------------------------------------------
// Combined weight pre-convert: layer L image [n][260], k<256 = [Wl_L;Wr_L]
// ---------------------------------------------------------------------------
__global__ void __launch_bounds__(256) convert_B_all(
    const float* __restrict__ Wl0, const float* __restrict__ Wr0,
    const float* __restrict__ Wl1, const float* __restrict__ Wr1,
    const float* __restrict__ Wl2, const float* __restrict__ Wr2,
    float* __restrict__ img)
{
    int L = blockIdx.x >> 7;
    int idx = (blockIdx.x & 127) * 256 + threadIdx.x;
    int n = idx >> 8;
    int k = idx & 255;
    const float* Wl = (L == 0) ? Wl0 : (L == 1) ? Wl1 : Wl2;
    const float* Wr = (L == 0) ? Wr0 : (L == 1) ? Wr1 : Wr2;
    float w = (k < 128) ? Wl[n * 128 + k] : Wr[n * 128 + (k - 128)];
    *(uint32_t*)&img[(size_t)L * IMG_WORDS + n * 260 + k] = f2tf32(w);
}

// ---------------------------------------------------------------------------
// Layer-0 persistent dual GEMM (round-8 verified control):
// 512 threads, 16 warps (4m x 4n), tile 128x128, K=256.
// ---------------------------------------------------------------------------
#define AS_STRIDE 36
#define BS_STRIDE 260
#define AS_WORDS  (128 * AS_STRIDE)
#define BS_WORDS  (128 * BS_STRIDE)
#define SMEM_G0 ((BS_WORDS + 4 * AS_WORDS) * 4)      // 206848

__global__ void __launch_bounds__(512, 1) gemm_persist(
    const float* __restrict__ Aagg, const float* __restrict__ X,
    const float* __restrict__ Bimg, float* __restrict__ out, int numTiles)
{
    extern __shared__ uint32_t smem[];
    uint32_t* Bs = smem;
    uint32_t* As = smem + BS_WORDS;

    const int tid  = threadIdx.x;
    const int lane = tid & 31;
    const int wid  = tid >> 5;
    const int wm   = wid & 3;
    const int wn   = wid >> 2;

    const uint32_t as_base = (uint32_t)__cvta_generic_to_shared(As);
    const uint32_t bs_base = (uint32_t)__cvta_generic_to_shared(Bs);

#pragma unroll
    for (int i = 0; i < 17; i++) {
        int e = i * 512 + tid;
        if (e < 128 * 65)
            cp_async16(bs_base + (uint32_t)e * 16,
                       (const uint8_t*)Bimg + (size_t)e * 16);
    }
    asm volatile("cp.async.commit_group;" ::);

    const int myTiles = (numTiles - blockIdx.x + gridDim.x - 1) / gridDim.x;
    const int totalQ  = myTiles * 8;

    auto issue = [&](int q) {
        const int cc = q & 7;
        const long blockM = (long)(blockIdx.x + (q >> 3) * gridDim.x) * 128;
        const float* src = (cc < 4) ? Aagg : X;
        const int koff = (cc & 3) * 32;
        const uint32_t sbase = as_base + (uint32_t)(q & 3) * (AS_WORDS * 4);
#pragma unroll
        for (int i = 0; i < 2; i++) {
            int idx = i * 512 + tid;
            int seg = idx & 7;
            int row = idx >> 3;
            cp_async16(sbase + (uint32_t)(row * (AS_STRIDE * 4) + seg * 16),
                       src + (blockM + row) * 128 + koff + seg * 4);
        }
        asm volatile("cp.async.commit_group;" ::);
    };

    issue(0); issue(1); issue(2); issue(3);

    float acc[2][4][4];
#pragma unroll
    for (int mi = 0; mi < 2; mi++)
#pragma unroll
        for (int ni = 0; ni < 4; ni++)
#pragma unroll
            for (int z = 0; z < 4; z++) acc[mi][ni][z] = 0.f;

    const uint32_t a_lane = (uint32_t)((wm * 32 + (lane & 15)) * (AS_STRIDE * 4)
                                       + (lane >> 4) * 16);
    const uint32_t b_lane = (uint32_t)((wn * 32 + (lane & 7)) * (BS_STRIDE * 4)
                                       + ((lane >> 3) & 1) * 16);

#pragma unroll 1
    for (int q = 0; q < totalQ; q++) {
        {
            int rem = totalQ - 1 - q;
            if (rem >= 3)      asm volatile("cp.async.wait_group 3;" ::);
            else if (rem == 2) asm volatile("cp.async.wait_group 2;" ::);
            else if (rem == 1) asm volatile("cp.async.wait_group 1;" ::);
            else               asm volatile("cp.async.wait_group 0;" ::);
        }
        __syncthreads();

        const uint32_t abuf = as_base + (uint32_t)(q & 3) * (AS_WORDS * 4);
        const int chunkK = (q & 7) * 32;
#pragma unroll
        for (int kb = 0; kb < 32; kb += 8) {
            const int gk = chunkK + kb;
            uint32_t bf[4][2];
#pragma unroll
            for (int ni = 0; ni < 4; ni++)
                ldsm_x2(bf[ni], bs_base + b_lane
                                + (uint32_t)(ni * 8 * BS_STRIDE * 4) + gk * 4);
            uint32_t af[2][4];
#pragma unroll
            for (int mi = 0; mi < 2; mi++) {
                ldsm_x4(af[mi], abuf + a_lane
                                + (uint32_t)(mi * 16 * AS_STRIDE * 4) + kb * 4);
#pragma unroll
                for (int z = 0; z < 4; z++)
                    asm volatile("cvt.rna.tf32.f32 %0, %0;" : "+r"(af[mi][z]));
            }
#pragma unroll
            for (int mi = 0; mi < 2; mi++)
#pragma unroll
                for (int ni = 0; ni < 4; ni++)
                    mma_tf32(acc[mi][ni], af[mi], bf[ni]);
        }
        __syncthreads();
        if (q + 4 < totalQ) issue(q + 4);

        if ((q & 7) == 7) {
            const long blockM = (long)(blockIdx.x + (q >> 3) * gridDim.x) * 128;
#pragma unroll
            for (int mi = 0; mi < 2; mi++) {
#pragma unroll
                for (int ni = 0; ni < 4; ni++) {
                    long row = blockM + wm * 32 + mi * 16 + (lane >> 2);
                    int  col = wn * 32 + ni * 8 + (lane & 3) * 2;
                    float2 lo = make_float2(fmaxf(acc[mi][ni][0], 0.f),
                                            fmaxf(acc[mi][ni][1], 0.f));
                    float2 hi = make_float2(fmaxf(acc[mi][ni][2], 0.f),
                                            fmaxf(acc[mi][ni][3], 0.f));
                    *(float2*)(out + row * 128 + col)       = lo;
                    *(float2*)(out + (row + 8) * 128 + col) = hi;
                    acc[mi][ni][0] = acc[mi][ni][1] = 0.f;
                    acc[mi][ni][2] = acc[mi][ni][3] = 0.f;
                }
            }
        }
    }
}

// ---------------------------------------------------------------------------
// N-split dual GEMM for small layers: tile 128m x 64n, K=256.
// grid = numMTiles * 2; block b: mt = b>>1, half = b&1 computes
// out[mt*128 .. +128, half*64 .. +64]. 16 warps: 4m x 4n, warp tile 32x16.
// RELU templated. Disjoint outputs -> no extra traffic.
// ---------------------------------------------------------------------------
#define NS_BS_WORDS (64 * BS_STRIDE)
#define SMEM_NS ((NS_BS_WORDS + 4 * AS_WORDS) * 4)   // 140288

template <int RELU>
__global__ void __launch_bounds__(512, 1) gemm_ns(
    const float* __restrict__ Aagg, const float* __restrict__ X,
    const float* __restrict__ Bimg, float* __restrict__ out)
{
    extern __shared__ uint32_t smem[];
    uint32_t* Bs = smem;                 // [64 n][260]
    uint32_t* As = smem + NS_BS_WORDS;   // [4][128 m][36]

    const int tid  = threadIdx.x;
    const int lane = tid & 31;
    const int wid  = tid >> 5;
    const int wm   = wid & 3;            // 4 warp rows x 32 m
    const int wn   = wid >> 2;           // 4 warp cols x 16 n
    const int half = blockIdx.x & 1;
    const long blockM = (long)(blockIdx.x >> 1) * 128;

    const uint32_t as_base = (uint32_t)__cvta_generic_to_shared(As);
    const uint32_t bs_base = (uint32_t)__cvta_generic_to_shared(Bs);

    // ---- stage this N-half of B (64 rows x 65 segs) ----
    const uint8_t* bsrc = (const uint8_t*)(Bimg + (size_t)half * 64 * BS_STRIDE);
#pragma unroll
    for (int i = 0; i < 9; i++) {
        int e = i * 512 + tid;
        if (e < 64 * 65)
            cp_async16(bs_base + (uint32_t)e * 16, bsrc + (size_t)e * 16);
    }
    asm volatile("cp.async.commit_group;" ::);

    // A chunks: 8 of 32 k (0-3: Agg, 4-7: X), 4-buffer ring
    auto issue = [&](int q) {
        const float* src = (q < 4) ? Aagg : X;
        const int koff = (q & 3) * 32;
        const uint32_t sbase = as_base + (uint32_t)(q & 3) * (AS_WORDS * 4);
#pragma unroll
        for (int i = 0; i < 2; i++) {
            int idx = i * 512 + tid;
            int seg = idx & 7;
            int row = idx >> 3;
            cp_async16(sbase + (uint32_t)(row * (AS_STRIDE * 4) + seg * 16),
                       src + (blockM + row) * 128 + koff + seg * 4);
        }
        asm volatile("cp.async.commit_group;" ::);
    };

    issue(0); issue(1); issue(2); issue(3);

    float acc[2][2][4];
#pragma unroll
    for (int mi = 0; mi < 2; mi++)
#pragma unroll
        for (int ni = 0; ni < 2; ni++)
#pragma unroll
            for (int z = 0; z < 4; z++) acc[mi][ni][z] = 0.f;

    const uint32_t a_lane = (uint32_t)((wm * 32 + (lane & 15)) * (AS_STRIDE * 4)
                                       + (lane >> 4) * 16);
    const uint32_t b_lane = (uint32_t)((wn * 16 + (lane & 7)) * (BS_STRIDE * 4)
                                       + ((lane >> 3) & 1) * 16);

#pragma unroll 1
    for (int q = 0; q < 8; q++) {
        {
            int rem = 7 - q;
            if (rem >= 3)      asm volatile("cp.async.wait_group 3;" ::);
            else if (rem == 2) asm volatile("cp.async.wait_group 2;" ::);
            else if (rem == 1) asm volatile("cp.async.wait_group 1;" ::);
            else               asm volatile("cp.async.wait_group 0;" ::);
        }
        __syncthreads();

        const uint32_t abuf = as_base + (uint32_t)(q & 3) * (AS_WORDS * 4);
        const int chunkK = q * 32;
#pragma unroll
        for (int kb = 0; kb < 32; kb += 8) {
            const int gk = chunkK + kb;
            uint32_t bf[2][2];
#pragma unroll
            for (int ni = 0; ni < 2; ni++)
                ldsm_x2(bf[ni], bs_base + b_lane
                                + (uint32_t)(ni * 8 * BS_STRIDE * 4) + gk * 4);
            uint32_t af[2][4];
#pragma unroll
            for (int mi = 0; mi < 2; mi++) {
                ldsm_x4(af[mi], abuf + a_lane
                                + (uint32_t)(mi * 16 * AS_STRIDE * 4) + kb * 4);
#pragma unroll
                for (int z = 0; z < 4; z++)
                    asm volatile("cvt.rna.tf32.f32 %0, %0;" : "+r"(af[mi][z]));
            }
#pragma unroll
            for (int mi = 0; mi < 2; mi++)
#pragma unroll
                for (int ni = 0; ni < 2; ni++)
                    mma_tf32(acc[mi][ni], af[mi], bf[ni]);
        }
        __syncthreads();
        if (q + 4 < 8) issue(q + 4);
    }

#pragma unroll
    for (int mi = 0; mi < 2; mi++) {
#pragma unroll
        for (int ni = 0; ni < 2; ni++) {
            long row = blockM + wm * 32 + mi * 16 + (lane >> 2);
            int  col = half * 64 + wn * 16 + ni * 8 + (lane & 3) * 2;
            float2 lo = make_float2(acc[mi][ni][0], acc[mi][ni][1]);
            float2 hi = make_float2(acc[mi][ni][2], acc[mi][ni][3]);
            if (RELU) {
                lo.x = fmaxf(lo.x, 0.f); lo.y = fmaxf(lo.y, 0.f);
                hi.x = fmaxf(hi.x, 0.f); hi.y = fmaxf(hi.y, 0.f);
            }
            *(float2*)(out + row * 128 + col)       = lo;
            *(float2*)(out + (row + 8) * 128 + col) = hi;
        }
    }
}

// ---------------------------------------------------------------------------
// log_softmax over rows of [1024, 128] (round-1 verified)
// ---------------------------------------------------------------------------
__global__ void __launch_bounds__(256) lsm_kernel(
    const float* __restrict__ in, float* __restrict__ out)
{
    int row  = blockIdx.x * 8 + (threadIdx.x >> 5);
    int lane = threadIdx.x & 31;
    if (row >= N3_NODES) return;

    float4 v = reinterpret_cast<const float4*>(in)[(long)row * 32 + lane];

    float m = fmaxf(fmaxf(v.x, v.y), fmaxf(v.z, v.w));
#pragma unroll
    for (int o = 16; o > 0; o >>= 1)
        m = fmaxf(m, __shfl_xor_sync(0xFFFFFFFF, m, o));

    float s = expf(v.x - m) + expf(v.y - m) + expf(v.z - m) + expf(v.w - m);
#pragma unroll
    for (int o = 16; o > 0; o >>= 1)
        s += __shfl_xor_sync(0xFFFFFFFF, s, o);

    float lse = m + logf(s);
    float4 r = make_float4(v.x - lse, v.y - lse, v.z - lse, v.w - lse);
    reinterpret_cast<float4*>(out)[(long)row * 32 + lane] = r;
}

// ---------------------------------------------------------------------------
// Launch
// ---------------------------------------------------------------------------
extern "C" void kernel_launch(void* const* d_in, const int* in_sizes, int n_in,
                              void* d_out, int out_size)
{
    const long X_SZ = (long)N0_NODES * D;
    const int  W_SZ = D * D;

    const float* x = nullptr;
    const float* Wl[3] = {nullptr, nullptr, nullptr};
    const float* Wr[3] = {nullptr, nullptr, nullptr};
    const int*   src[3] = {nullptr, nullptr, nullptr};

    if ((long)in_sizes[0] == X_SZ && in_sizes[1] == W_SZ) {
        x = (const float*)d_in[0];
        for (int i = 0; i < 3; i++) {
            Wl[i]  = (const float*)d_in[1 + 2 * i];
            Wr[i]  = (const float*)d_in[2 + 2 * i];
            src[i] = (const int*)  d_in[7 + 2 * i];
        }
    } else if ((long)in_sizes[0] == X_SZ) {
        x = (const float*)d_in[0];
        for (int i = 0; i < 3; i++) {
            src[i] = (const int*)  d_in[1 + 4 * i];
            Wl[i]  = (const float*)d_in[3 + 4 * i];
            Wr[i]  = (const float*)d_in[4 + 4 * i];
        }
    } else {
        for (int i = 0; i < 3; i++) {
            Wl[i]  = (const float*)d_in[i];
            Wr[i]  = (const float*)d_in[3 + i];
            src[i] = (const int*)  d_in[9 + i];
        }
        x = (const float*)d_in[12];
    }

    float *agg, *h1, *h2, *bimg;
    cudaGetSymbolAddress((void**)&agg,  g_agg);
    cudaGetSymbolAddress((void**)&h1,   g_h1);
    cudaGetSymbolAddress((void**)&h2,   g_h2);
    cudaGetSymbolAddress((void**)&bimg, g_Bimg);

    // One-time side stream + events (round-9 verified capture-legal pattern)
    static cudaStream_t s2 = nullptr;
    static cudaEvent_t evF = nullptr, evJ = nullptr;
    if (!s2) {
        cudaStreamCreateWithFlags(&s2, cudaStreamNonBlocking);
        cudaEventCreateWithFlags(&evF, cudaEventDisableTiming);
        cudaEventCreateWithFlags(&evJ, cudaEventDisableTiming);
    }

    cudaFuncSetAttribute(gemm_persist,
        cudaFuncAttributeMaxDynamicSharedMemorySize, SMEM_G0);
    cudaFuncSetAttribute(gemm_ns<1>,
        cudaFuncAttributeMaxDynamicSharedMemorySize, SMEM_NS);
    cudaFuncSetAttribute(gemm_ns<0>,
        cudaFuncAttributeMaxDynamicSharedMemorySize, SMEM_NS);

    float* out = (float*)d_out;
    const int T0 = N1_NODES / 128;   // 528 = 132 * 4

    // Convert weights on side stream, overlapped with the big gather
    cudaEventRecord(evF, 0);
    cudaStreamWaitEvent(s2, evF, 0);
    convert_B_all<<<384, 256, 0, s2>>>(Wl[0], Wr[0], Wl[1], Wr[1],
                                       Wl[2], Wr[2], bimg);

    // Layer 0: roofline gather + persistent dual GEMM
    agg_kernel<F0><<<N1_NODES / 8, 256>>>(x, src[0], agg, N1_NODES);
    cudaEventRecord(evJ, s2);
    cudaStreamWaitEvent(0, evJ, 0);
    gemm_persist<<<132, 512, SMEM_G0>>>(agg, x, bimg, h1, T0);

    // Layer 1: gather + N-split dual GEMM (96 blocks) + ReLU
    agg_kernel<F1><<<N2_NODES / 8, 256>>>(h1, src[1], agg, N2_NODES);
    gemm_ns<1><<<(N2_NODES / 128) * 2, 512, SMEM_NS>>>(
        agg, h1, bimg + IMG_WORDS, h2);

    // Layer 2: gather + N-split dual GEMM (16 blocks) -> logits in g_h1
    agg_kernel<F2><<<N3_NODES / 8, 256>>>(h2, src[2], agg, N3_NODES);
    gemm_ns<0><<<(N3_NODES / 128) * 2, 512, SMEM_NS>>>(
        agg, h2, bimg + 2 * IMG_WORDS, h1);

    // log_softmax
    lsm_kernel<<<N3_NODES / 8, 256>>>(h1, out);
}